// round 8
// baseline (speedup 1.0000x reference)
#include <cuda_runtime.h>
#include <cstdint>

#define V_NODES   1000000
#define N_GRAPHS  50000
#define NODE_DIM  128
#define HIDDEN    128
#define GDIM      64
#define NT_TILES  7813          // ceil(1e6 / 128)
#define GRID_N    152           // persistent CTAs (GB300: 152 SMs)

// ---------------- scratch ----------------
__device__ __align__(256) float    g_Z1[(size_t)N_GRAPHS * HIDDEN];
__device__ __align__(256) float    g_cnt[N_GRAPHS];
__device__ __align__(256) unsigned g_Wtf[256 * NODE_DIM];   // W1/W2 interleaved, tf32 bits
__device__ int g_is64;

// ---------------- helpers ----------------
__device__ __forceinline__ unsigned f2tf(float f) {
    unsigned u;
    asm("cvt.rna.tf32.f32 %0, %1;" : "=r"(u) : "f"(f));
    return u;
}

__device__ __forceinline__ void mma_tf32(float& c0, float& c1, float& c2, float& c3,
                                         unsigned a0, unsigned a1, unsigned a2, unsigned a3,
                                         unsigned b0, unsigned b1) {
    asm volatile(
        "mma.sync.aligned.m16n8k8.row.col.f32.tf32.tf32.f32 "
        "{%0,%1,%2,%3},{%4,%5,%6,%7},{%8,%9},{%0,%1,%2,%3};"
        : "+f"(c0), "+f"(c1), "+f"(c2), "+f"(c3)
        : "r"(a0), "r"(a1), "r"(a2), "r"(a3), "r"(b0), "r"(b1));
}

__device__ __forceinline__ void red4(float* p, float4 v) {
    asm volatile("red.global.add.v4.f32 [%0], {%1,%2,%3,%4};"
                 :: "l"(p), "f"(v.x), "f"(v.y), "f"(v.z), "f"(v.w) : "memory");
}

__device__ __forceinline__ float sigm(float x) { return 1.0f / (1.0f + __expf(-x)); }

__device__ __forceinline__ unsigned s2u(const void* p) {
    return (unsigned)__cvta_generic_to_shared(p);
}

__device__ __forceinline__ void cp16(unsigned dst, const void* src, unsigned sz) {
    asm volatile("cp.async.cg.shared.global [%0], [%1], 16, %2;"
                 :: "r"(dst), "l"(src), "r"(sz));
}
__device__ __forceinline__ void cp_commit() {
    asm volatile("cp.async.commit_group;");
}
template <int N>
__device__ __forceinline__ void cp_wait() {
    asm volatile("cp.async.wait_group %0;" :: "n"(N));
}

// ---------------- kernel 0: zero + dtype detect + W pre-convert ----------------
__global__ void k_init(const unsigned* __restrict__ n2g_words,
                       const float* __restrict__ W1, const float* __restrict__ W2) {
    if (blockIdx.x == 0) {
        __shared__ int nz;
        if (threadIdx.x == 0) nz = 0;
        __syncthreads();
        unsigned acc = 0;
        #pragma unroll
        for (int q = 0; q < 4; ++q)
            acc |= n2g_words[2 * (threadIdx.x * 4 + q) + 1];   // idx <= 2047
        if (acc != 0u) atomicOr(&nz, 1);
        __syncthreads();
        if (threadIdx.x == 0) g_is64 = (nz == 0) ? 1 : 0;
    }
    size_t i = (size_t)blockIdx.x * blockDim.x + threadIdx.x;
    size_t stride = (size_t)gridDim.x * blockDim.x;

    for (size_t k = i; k < 256 * NODE_DIM; k += stride) {
        int r = (int)(k >> 7), c = (int)(k & 127);
        const float* src = (r & 1) ? W2 : W1;
        g_Wtf[k] = f2tf(src[(r >> 1) * NODE_DIM + c]);
    }

    float4* z = reinterpret_cast<float4*>(g_Z1);
    const size_t n4 = (size_t)N_GRAPHS * HIDDEN / 4;
    for (size_t k = i; k < n4; k += stride) z[k] = make_float4(0.f, 0.f, 0.f, 0.f);
    for (size_t k = i; k < N_GRAPHS; k += stride) g_cnt[k] = 0.f;
}

// ---------------- kernel 1: persistent node MLP (gated) + per-node scatter ----------------
// 152 persistent CTAs x 512 thr. W resident in smem once per CTA (stride 132).
// X streamed through 4 smem stages, lookahead 3 commit-groups (~55KB always in
// flight per SM -> DRAM saturated). One syncthreads per K-chunk. Epilogue in
// four 32-row quarters through a small HSQ buffer; per-node red4 (R6 semantics).
#define WT_FL   (256 * 132)              // 33792 floats
#define XSTG_FL (128 * 36)               // 4608 floats per stage
#define HSQ_FL  (32 * 132)               // 4224 floats
#define SMEM_NODES_FL (WT_FL + 4*XSTG_FL + HSQ_FL + 128 + 128 + 128)
#define SMEM_NODES_BYTES (SMEM_NODES_FL * 4)   // 227,328 B

__global__ __launch_bounds__(512, 1)
void k_nodes(const float* __restrict__ x, const void* __restrict__ n2g,
             const float* __restrict__ b1, const float* __restrict__ b2) {
    extern __shared__ float smem[];
    float* WT  = smem;                        // [256*132]
    float* XS  = smem + WT_FL;                // [4][128*36]
    float* HSQ = smem + WT_FL + 4 * XSTG_FL;  // [32*132]
    float* B1S = HSQ + HSQ_FL;
    float* B2S = B1S + 128;
    int*   GID = reinterpret_cast<int*>(B2S + 128);

    const int tid = threadIdx.x;
    const int lane = tid & 31;
    const int wid = tid >> 5;
    const int wm = wid >> 2;
    const int wn = wid & 3;
    const int bid = blockIdx.x;
    const int is64 = g_is64;

    // group 0: resident W (pre-converted tf32 bits), one copy per CTA lifetime
    #pragma unroll
    for (int p = 0; p < 16; ++p) {
        int idx = p * 512 + tid;
        int r = idx >> 5, c4 = idx & 31;
        cp16(s2u(WT + r * 132 + c4 * 4), g_Wtf + r * 128 + c4 * 4, 16u);
    }
    cp_commit();

    const int ntiles = (NT_TILES - bid + GRID_N - 1) / GRID_N;
    const int Ntot = ntiles * 4;

    auto issueX = [&](int q) {
        int t = q >> 2, kc = q & 3;
        int node0 = (bid + t * GRID_N) * 128;
        float* XSb = XS + kc * XSTG_FL;       // stage == kc (4 chunks, 4 stages)
        #pragma unroll
        for (int p = 0; p < 2; ++p) {
            int idx = p * 512 + tid;
            int r = idx >> 3, c4 = idx & 7;
            int node = node0 + r;
            unsigned sz = (node < V_NODES) ? 16u : 0u;   // sz=0 -> zero-fill
            int nc = (node < V_NODES) ? node : (V_NODES - 1);
            cp16(s2u(XSb + r * 36 + c4 * 4),
                 x + (size_t)nc * NODE_DIM + kc * 32 + c4 * 4, sz);
        }
        cp_commit();
    };

    // prologue: 3 chunks in flight (empty groups if degenerate)
    #pragma unroll
    for (int q = 0; q < 3; ++q) {
        if (q < Ntot) issueX(q); else cp_commit();
    }

    if (tid < 128)       B1S[tid]       = b1[tid];
    else if (tid < 256)  B2S[tid - 128] = b2[tid - 128];

    const int ro = lane >> 2;
    const int col0 = lane & 3;
    const unsigned* WTu = reinterpret_cast<const unsigned*>(WT);

    for (int t = 0; t < ntiles; ++t) {
        const int node0 = (bid + t * GRID_N) * 128;

        int mygid = -1;
        if (tid < 128) {
            int node = node0 + tid;
            if (node < V_NODES)
                mygid = is64 ? (int)reinterpret_cast<const long long*>(n2g)[node]
                             : reinterpret_cast<const int*>(n2g)[node];
        }

        float c[2][8][4];
        #pragma unroll
        for (int mi = 0; mi < 2; ++mi)
            #pragma unroll
            for (int ni = 0; ni < 8; ++ni)
                #pragma unroll
                for (int q = 0; q < 4; ++q) c[mi][ni][q] = 0.f;

        #pragma unroll
        for (int kc = 0; kc < 4; ++kc) {
            cp_wait<2>();          // invariant: lookahead 3 -> chunk kc complete
            __syncthreads();       // visibility + releases stage (kc-1)%4 for write

            const float* XSf = XS + kc * XSTG_FL;
            #pragma unroll
            for (int ks = 0; ks < 4; ++ks) {
                const int co = ks * 8 + col0;
                unsigned a[2][4];
                #pragma unroll
                for (int mi = 0; mi < 2; ++mi) {
                    int rb = wm * 32 + mi * 16;
                    a[mi][0] = f2tf(XSf[(rb + ro) * 36 + co]);
                    a[mi][1] = f2tf(XSf[(rb + ro + 8) * 36 + co]);
                    a[mi][2] = f2tf(XSf[(rb + ro) * 36 + co + 4]);
                    a[mi][3] = f2tf(XSf[(rb + ro + 8) * 36 + co + 4]);
                }
                const int wco = kc * 32 + ks * 8 + col0;
                #pragma unroll
                for (int ni = 0; ni < 8; ++ni) {
                    int nr = wn * 64 + ni * 8 + ro;
                    unsigned bb0 = WTu[nr * 132 + wco];
                    unsigned bb1 = WTu[nr * 132 + wco + 4];
                    mma_tf32(c[0][ni][0], c[0][ni][1], c[0][ni][2], c[0][ni][3],
                             a[0][0], a[0][1], a[0][2], a[0][3], bb0, bb1);
                    mma_tf32(c[1][ni][0], c[1][ni][1], c[1][ni][2], c[1][ni][3],
                             a[1][0], a[1][1], a[1][2], a[1][3], bb0, bb1);
                }
            }

            int qn = t * 4 + kc + 3;
            if (qn < Ntot) issueX(qn); else cp_commit();   // keep lookahead exact
        }

        if (tid < 128) {
            GID[tid] = mygid;
            if (mygid >= 0) atomicAdd(&g_cnt[mygid], 1.0f);
        }

        // epilogue: four 32-row quarters through HSQ
        #pragma unroll
        for (int qt = 0; qt < 4; ++qt) {
            __syncthreads();       // GID visible (qt=0); prev quarter reads done
            if (wm == qt) {
                #pragma unroll
                for (int ni = 0; ni < 8; ++ni) {
                    int j = wn * 32 + ni * 4 + col0;
                    float bb1 = B1S[j], bb2 = B2S[j];
                    HSQ[ro * 132 + j]        = (c[0][ni][0] + bb1) * sigm(c[0][ni][1] + bb2);
                    HSQ[(ro + 8) * 132 + j]  = (c[0][ni][2] + bb1) * sigm(c[0][ni][3] + bb2);
                    HSQ[(ro + 16) * 132 + j] = (c[1][ni][0] + bb1) * sigm(c[1][ni][1] + bb2);
                    HSQ[(ro + 24) * 132 + j] = (c[1][ni][2] + bb1) * sigm(c[1][ni][3] + bb2);
                }
            }
            __syncthreads();
            #pragma unroll
            for (int p = 0; p < 2; ++p) {
                int idx = p * 512 + tid;
                int r = idx >> 5, cc = idx & 31;
                int g = GID[qt * 32 + r];
                if (g >= 0) {
                    float4 v = *reinterpret_cast<const float4*>(HSQ + r * 132 + cc * 4);
                    red4(&g_Z1[(size_t)g * HIDDEN + cc * 4], v);
                }
            }
        }
    }
}

// ---------------- kernel 2: readout GEMM (unchanged from R6) ----------------
#define G_STAGE_FL (128*36 + 128*36)
#define SMEM_GRAPHS_FL (3*G_STAGE_FL + 128 + 128)
#define SMEM_GRAPHS_BYTES (SMEM_GRAPHS_FL * 4)

__global__ __launch_bounds__(256, 2)
void k_graphs(const float* __restrict__ gx, const float* __restrict__ W3,
              const float* __restrict__ b3, float* __restrict__ out) {
    extern __shared__ float smem[];
    float* SS  = smem + 3 * G_STAGE_FL;
    float* B3S = SS + 128;

    const int tid = threadIdx.x;
    const int lane = tid & 31;
    const int wid = tid >> 5;
    const int wm = wid >> 2;
    const int wn = wid & 3;
    const int g0 = blockIdx.x * 128;

    auto issue = [&](int kc, int buf) {
        float* ZSb = smem + buf * G_STAGE_FL;
        float* WSb = ZSb + 128 * 36;
        #pragma unroll
        for (int p = 0; p < 4; ++p) {
            int idx = p * 256 + tid;
            int r = idx >> 3, c4 = idx & 7;
            int g = g0 + r;
            unsigned sz = (g < N_GRAPHS) ? 16u : 0u;
            int gc = (g < N_GRAPHS) ? g : (N_GRAPHS - 1);
            const float* src;
            if (kc < 4)      src = g_Z1 + (size_t)gc * HIDDEN + kc * 32 + c4 * 4;
            else if (kc < 8) src = g_Z1 + (size_t)gc * HIDDEN + (kc - 4) * 32 + c4 * 4;
            else             src = gx + (size_t)gc * GDIM + (kc - 8) * 32 + c4 * 4;
            cp16(s2u(ZSb + r * 36 + c4 * 4), src, sz);
        }
        #pragma unroll
        for (int p = 0; p < 4; ++p) {
            int idx = p * 256 + tid;
            int j = idx >> 3, c4 = idx & 7;
            cp16(s2u(WSb + j * 36 + c4 * 4),
                 W3 + (size_t)j * 320 + kc * 32 + c4 * 4, 16u);
        }
        cp_commit();
    };

    issue(0, 0);
    issue(1, 1);

    if (tid < 128) {
        int g = g0 + tid;
        float cn = (g < N_GRAPHS) ? g_cnt[g] : 1.0f;
        SS[tid] = 1.0f / fmaxf(cn, 1.0f);
        B3S[tid] = b3[tid];
    }

    float c[4][4][4];
    #pragma unroll
    for (int mi = 0; mi < 4; ++mi)
        #pragma unroll
        for (int ni = 0; ni < 4; ++ni)
            #pragma unroll
            for (int q = 0; q < 4; ++q) c[mi][ni][q] = 0.f;

    const int ro = lane >> 2;
    const int col0 = lane & 3;

    for (int kc = 0; kc < 10; ++kc) {
        if (kc < 9) cp_wait<1>(); else cp_wait<0>();
        __syncthreads();

        const float* ZSf = smem + (kc % 3) * G_STAGE_FL;
        const float* WSf = ZSf + 128 * 36;
        const bool isZ2 = (kc >= 4) && (kc < 8);

        float s0[4], s1[4];
        #pragma unroll
        for (int mi = 0; mi < 4; ++mi) {
            int rb = wm * 64 + mi * 16;
            s0[mi] = isZ2 ? SS[rb + ro]     : 1.0f;
            s1[mi] = isZ2 ? SS[rb + ro + 8] : 1.0f;
        }

        #pragma unroll
        for (int ks = 0; ks < 4; ++ks) {
            const int co = ks * 8 + col0;
            unsigned a[4][4];
            #pragma unroll
            for (int mi = 0; mi < 4; ++mi) {
                int rb = wm * 64 + mi * 16;
                a[mi][0] = f2tf(ZSf[(rb + ro) * 36 + co]     * s0[mi]);
                a[mi][1] = f2tf(ZSf[(rb + ro + 8) * 36 + co] * s1[mi]);
                a[mi][2] = f2tf(ZSf[(rb + ro) * 36 + co + 4]     * s0[mi]);
                a[mi][3] = f2tf(ZSf[(rb + ro + 8) * 36 + co + 4] * s1[mi]);
            }
            #pragma unroll
            for (int ni = 0; ni < 4; ++ni) {
                int nr = wn * 32 + ni * 8 + ro;
                unsigned bb0 = f2tf(WSf[nr * 36 + co]);
                unsigned bb1 = f2tf(WSf[nr * 36 + co + 4]);
                #pragma unroll
                for (int mi = 0; mi < 4; ++mi)
                    mma_tf32(c[mi][ni][0], c[mi][ni][1], c[mi][ni][2], c[mi][ni][3],
                             a[mi][0], a[mi][1], a[mi][2], a[mi][3], bb0, bb1);
            }
        }

        if (kc + 2 <= 9) issue(kc + 2, (kc + 2) % 3);
    }

    #pragma unroll
    for (int mi = 0; mi < 4; ++mi) {
        #pragma unroll
        for (int ni = 0; ni < 4; ++ni) {
            int r = wm * 64 + mi * 16 + ro;
            int n = wn * 32 + ni * 8 + 2 * col0;
            int g = g0 + r;
            if (g < N_GRAPHS) {
                float2 v;
                v.x = fmaxf(c[mi][ni][0] + B3S[n], 0.f);
                v.y = fmaxf(c[mi][ni][1] + B3S[n + 1], 0.f);
                *reinterpret_cast<float2*>(out + (size_t)g * 128 + n) = v;
            }
            int g2 = g0 + r + 8;
            if (g2 < N_GRAPHS) {
                float2 v;
                v.x = fmaxf(c[mi][ni][2] + B3S[n], 0.f);
                v.y = fmaxf(c[mi][ni][3] + B3S[n + 1], 0.f);
                *reinterpret_cast<float2*>(out + (size_t)g2 * 128 + n) = v;
            }
        }
    }
}

// ---------------- launch ----------------
extern "C" void kernel_launch(void* const* d_in, const int* in_sizes, int n_in,
                              void* d_out, int out_size) {
    const float* x  = (const float*)d_in[0];
    const void*  n2g = d_in[1];
    const float* gx = (const float*)d_in[2];
    const float* W1 = (const float*)d_in[3];
    const float* b1 = (const float*)d_in[4];
    const float* W2 = (const float*)d_in[5];
    const float* b2 = (const float*)d_in[6];
    const float* W3 = (const float*)d_in[7];
    const float* b3 = (const float*)d_in[8];
    float* out = (float*)d_out;

    static bool attr_set = false;
    if (!attr_set) {
        cudaFuncSetAttribute(k_nodes, cudaFuncAttributeMaxDynamicSharedMemorySize,
                             SMEM_NODES_BYTES);
        cudaFuncSetAttribute(k_graphs, cudaFuncAttributeMaxDynamicSharedMemorySize,
                             SMEM_GRAPHS_BYTES);
        attr_set = true;
    }

    k_init<<<2048, 256>>>((const unsigned*)n2g, W1, W2);
    k_nodes<<<GRID_N, 512, SMEM_NODES_BYTES>>>(x, n2g, b1, b2);
    k_graphs<<<(N_GRAPHS + 127) / 128, 256, SMEM_GRAPHS_BYTES>>>(gx, W3, b3, out);
}

// round 10
// speedup vs baseline: 1.4189x; 1.4189x over previous
#include <cuda_runtime.h>
#include <cstdint>

#define V_NODES   1000000
#define N_GRAPHS  50000
#define NODE_DIM  128
#define HIDDEN    128
#define GDIM      64

// ---------------- scratch ----------------
__device__ __align__(256) float g_Z1[(size_t)N_GRAPHS * HIDDEN];
__device__ __align__(256) float g_cnt[N_GRAPHS];
__device__ __align__(256) uint2 g_Wp[256 * 68];   // W1/W2 interleaved, tf32 bit-pairs (w[k], w[k+4]), stride 68
__device__ int g_is64;

// ---------------- helpers ----------------
__device__ __forceinline__ unsigned f2tf(float f) {
    unsigned u;
    asm("cvt.rna.tf32.f32 %0, %1;" : "=r"(u) : "f"(f));
    return u;
}

__device__ __forceinline__ void mma_tf32(float& c0, float& c1, float& c2, float& c3,
                                         unsigned a0, unsigned a1, unsigned a2, unsigned a3,
                                         unsigned b0, unsigned b1) {
    asm volatile(
        "mma.sync.aligned.m16n8k8.row.col.f32.tf32.tf32.f32 "
        "{%0,%1,%2,%3},{%4,%5,%6,%7},{%8,%9},{%0,%1,%2,%3};"
        : "+f"(c0), "+f"(c1), "+f"(c2), "+f"(c3)
        : "r"(a0), "r"(a1), "r"(a2), "r"(a3), "r"(b0), "r"(b1));
}

__device__ __forceinline__ void red4(float* p, float4 v) {
    asm volatile("red.global.add.v4.f32 [%0], {%1,%2,%3,%4};"
                 :: "l"(p), "f"(v.x), "f"(v.y), "f"(v.z), "f"(v.w) : "memory");
}

__device__ __forceinline__ float sigm(float x) { return 1.0f / (1.0f + __expf(-x)); }

__device__ __forceinline__ unsigned s2u(const void* p) {
    return (unsigned)__cvta_generic_to_shared(p);
}

__device__ __forceinline__ void cp16(unsigned dst, const void* src, unsigned sz) {
    asm volatile("cp.async.cg.shared.global [%0], [%1], 16, %2;"
                 :: "r"(dst), "l"(src), "r"(sz));
}
__device__ __forceinline__ void cp_commit() {
    asm volatile("cp.async.commit_group;");
}
template <int N>
__device__ __forceinline__ void cp_wait() {
    asm volatile("cp.async.wait_group %0;" :: "n"(N));
}

// ---------------- kernel 0: zero + dtype detect + W pre-convert (paired) ----------------
__global__ void k_init(const unsigned* __restrict__ n2g_words,
                       const float* __restrict__ W1, const float* __restrict__ W2) {
    if (blockIdx.x == 0) {
        __shared__ int nz;
        if (threadIdx.x == 0) nz = 0;
        __syncthreads();
        unsigned acc = 0;
        #pragma unroll
        for (int q = 0; q < 4; ++q)
            acc |= n2g_words[2 * (threadIdx.x * 4 + q) + 1];   // idx <= 2047
        if (acc != 0u) atomicOr(&nz, 1);
        __syncthreads();
        if (threadIdx.x == 0) g_is64 = (nz == 0) ? 1 : 0;
    }
    size_t i = (size_t)blockIdx.x * blockDim.x + threadIdx.x;
    size_t stride = (size_t)gridDim.x * blockDim.x;

    // W pairs: row r (r=2j -> W1[j], r=2j+1 -> W2[j]); entry (kb,k') = (w[kb*8+k'], w[kb*8+k'+4])
    for (size_t k = i; k < 256 * 64; k += stride) {
        int r = (int)(k >> 6), t = (int)(k & 63);
        int kb = t >> 2, kp = t & 3;
        const float* src = (r & 1) ? W2 : W1;
        int j = r >> 1;
        g_Wp[r * 68 + t] = make_uint2(f2tf(src[j * 128 + kb * 8 + kp]),
                                      f2tf(src[j * 128 + kb * 8 + kp + 4]));
    }

    float4* z = reinterpret_cast<float4*>(g_Z1);
    const size_t n4 = (size_t)N_GRAPHS * HIDDEN / 4;
    for (size_t k = i; k < n4; k += stride) z[k] = make_float4(0.f, 0.f, 0.f, 0.f);
    for (size_t k = i; k < N_GRAPHS; k += stride) g_cnt[k] = 0.f;
}

// ---------------- pad kernels: steer ncu capture (launch #4 = k_nodes) ----------------
__global__ void k_pad() {}

// ---------------- kernel: node MLP (gated) + per-node scatter ----------------
// 128 nodes/block, N=256, K=128 in 4 chunks of 32. 512 thr = 16 warps, 4x4 warp
// grid, warp tile 32x64. W resident in smem as uint2 pairs -> LDS.64 fragments.
// X-only 3-stage cp.async pipeline; HS (gated h) aliases the X stages.
#define WT_U2   (256 * 68)               // 17408 uint2 = 139264 B
#define WT_FL   (WT_U2 * 2)              // in float units
#define XSTG_FL (128 * 36)               // one X stage
#define HS_FL   (128 * 132)              // aliases the 3 X stages (67.6KB >= 55.3KB)
#define SMEM_NODES_FL (WT_FL + HS_FL + 128 + 128 + 128)
#define SMEM_NODES_BYTES (SMEM_NODES_FL * 4)   // 208,384 B

__global__ __launch_bounds__(512, 1)
void k_nodes(const float* __restrict__ x, const void* __restrict__ n2g,
             const float* __restrict__ b1, const float* __restrict__ b2) {
    extern __shared__ float smem[];
    const uint2* WT2 = reinterpret_cast<const uint2*>(smem);   // [256*68]
    float* XS  = smem + WT_FL;            // [3][128*36] (inside HS region)
    float* HS  = smem + WT_FL;            // [128*132] after pipeline drains
    float* B1S = smem + WT_FL + HS_FL;
    float* B2S = B1S + 128;
    int*   GID = reinterpret_cast<int*>(B2S + 128);

    const int tid = threadIdx.x;
    const int lane = tid & 31;
    const int wid = tid >> 5;
    const int wm = wid >> 2;
    const int wn = wid & 3;
    const int node0 = blockIdx.x * 128;
    const int is64 = g_is64;

    // group 0: resident W copy (8704 x 16B, flat, pads included)
    #pragma unroll
    for (int p = 0; p < 17; ++p) {
        int idx = p * 512 + tid;
        cp16(s2u(reinterpret_cast<const char*>(smem) + idx * 16),
             reinterpret_cast<const char*>(g_Wp) + idx * 16, 16u);
    }
    cp_commit();

    auto issueX = [&](int kc, int buf) {
        float* XSb = XS + buf * XSTG_FL;
        #pragma unroll
        for (int p = 0; p < 2; ++p) {
            int idx = p * 512 + tid;
            int r = idx >> 3, c4 = idx & 7;
            int node = node0 + r;
            unsigned sz = (node < V_NODES) ? 16u : 0u;
            int nc = (node < V_NODES) ? node : (V_NODES - 1);
            cp16(s2u(XSb + r * 36 + c4 * 4),
                 x + (size_t)nc * NODE_DIM + kc * 32 + c4 * 4, sz);
        }
        cp_commit();
    };

    issueX(0, 0);
    issueX(1, 1);

    // bias + gid while copies fly
    if (tid < 128)       B1S[tid]       = b1[tid];
    else if (tid < 256)  B2S[tid - 128] = b2[tid - 128];
    if (tid < 128) {
        int node = node0 + tid;
        int g = -1;
        if (node < V_NODES) {
            g = is64 ? (int)reinterpret_cast<const long long*>(n2g)[node]
                     : reinterpret_cast<const int*>(n2g)[node];
            atomicAdd(&g_cnt[g], 1.0f);
        }
        GID[tid] = g;
    }

    float c[2][8][4];
    #pragma unroll
    for (int mi = 0; mi < 2; ++mi)
        #pragma unroll
        for (int ni = 0; ni < 8; ++ni)
            #pragma unroll
            for (int q = 0; q < 4; ++q) c[mi][ni][q] = 0.f;

    const int ro = lane >> 2;
    const int col0 = lane & 3;

    #pragma unroll
    for (int kc = 0; kc < 4; ++kc) {
        if (kc < 3) cp_wait<1>(); else cp_wait<0>();
        __syncthreads();          // chunk kc (and W) visible; stage (kc+2)%3 free

        const float* XSf = XS + (kc % 3) * XSTG_FL;
        #pragma unroll
        for (int ks = 0; ks < 4; ++ks) {
            const int co = ks * 8 + col0;
            unsigned a[2][4];
            #pragma unroll
            for (int mi = 0; mi < 2; ++mi) {
                int rb = wm * 32 + mi * 16;
                a[mi][0] = f2tf(XSf[(rb + ro) * 36 + co]);
                a[mi][1] = f2tf(XSf[(rb + ro + 8) * 36 + co]);
                a[mi][2] = f2tf(XSf[(rb + ro) * 36 + co + 4]);
                a[mi][3] = f2tf(XSf[(rb + ro + 8) * 36 + co + 4]);
            }
            const int kb4 = (kc * 4 + ks) * 4 + col0;
            #pragma unroll
            for (int ni = 0; ni < 8; ++ni) {
                int nr = wn * 64 + ni * 8 + ro;
                uint2 wv = WT2[nr * 68 + kb4];          // LDS.64: (w[co], w[co+4])
                mma_tf32(c[0][ni][0], c[0][ni][1], c[0][ni][2], c[0][ni][3],
                         a[0][0], a[0][1], a[0][2], a[0][3], wv.x, wv.y);
                mma_tf32(c[1][ni][0], c[1][ni][1], c[1][ni][2], c[1][ni][3],
                         a[1][0], a[1][1], a[1][2], a[1][3], wv.x, wv.y);
            }
        }

        if (kc + 2 <= 3) issueX(kc + 2, (kc + 2) % 3);
    }

    __syncthreads();   // X staging dead; HS aliases it

    // epilogue: gate -> HS (C col pairs: even=lin1[j], odd=lin2[j])
    #pragma unroll
    for (int ni = 0; ni < 8; ++ni) {
        int j = wn * 32 + ni * 4 + col0;
        float bb1 = B1S[j], bb2 = B2S[j];
        int r = wm * 32 + ro;
        HS[r * 132 + j]        = (c[0][ni][0] + bb1) * sigm(c[0][ni][1] + bb2);
        HS[(r + 8) * 132 + j]  = (c[0][ni][2] + bb1) * sigm(c[0][ni][3] + bb2);
        HS[(r + 16) * 132 + j] = (c[1][ni][0] + bb1) * sigm(c[1][ni][1] + bb2);
        HS[(r + 24) * 132 + j] = (c[1][ni][2] + bb1) * sigm(c[1][ni][3] + bb2);
    }
    __syncthreads();

    // vectorized scatter: 128 rows x 32 float4
    #pragma unroll
    for (int idx = tid; idx < 4096; idx += 512) {
        int r = idx >> 5, c4 = idx & 31;
        int g = GID[r];
        if (g >= 0) {
            float4 v = *reinterpret_cast<const float4*>(HS + r * 132 + c4 * 4);
            red4(&g_Z1[(size_t)g * HIDDEN + c4 * 4], v);
        }
    }
}

// ---------------- readout GEMM (unchanged from R6) ----------------
#define G_STAGE_FL (128*36 + 128*36)
#define SMEM_GRAPHS_FL (3*G_STAGE_FL + 128 + 128)
#define SMEM_GRAPHS_BYTES (SMEM_GRAPHS_FL * 4)

__global__ __launch_bounds__(256, 2)
void k_graphs(const float* __restrict__ gx, const float* __restrict__ W3,
              const float* __restrict__ b3, float* __restrict__ out) {
    extern __shared__ float smem[];
    float* SS  = smem + 3 * G_STAGE_FL;
    float* B3S = SS + 128;

    const int tid = threadIdx.x;
    const int lane = tid & 31;
    const int wid = tid >> 5;
    const int wm = wid >> 2;
    const int wn = wid & 3;
    const int g0 = blockIdx.x * 128;

    auto issue = [&](int kc, int buf) {
        float* ZSb = smem + buf * G_STAGE_FL;
        float* WSb = ZSb + 128 * 36;
        #pragma unroll
        for (int p = 0; p < 4; ++p) {
            int idx = p * 256 + tid;
            int r = idx >> 3, c4 = idx & 7;
            int g = g0 + r;
            unsigned sz = (g < N_GRAPHS) ? 16u : 0u;
            int gc = (g < N_GRAPHS) ? g : (N_GRAPHS - 1);
            const float* src;
            if (kc < 4)      src = g_Z1 + (size_t)gc * HIDDEN + kc * 32 + c4 * 4;
            else if (kc < 8) src = g_Z1 + (size_t)gc * HIDDEN + (kc - 4) * 32 + c4 * 4;
            else             src = gx + (size_t)gc * GDIM + (kc - 8) * 32 + c4 * 4;
            cp16(s2u(ZSb + r * 36 + c4 * 4), src, sz);
        }
        #pragma unroll
        for (int p = 0; p < 4; ++p) {
            int idx = p * 256 + tid;
            int j = idx >> 3, c4 = idx & 7;
            cp16(s2u(WSb + j * 36 + c4 * 4),
                 W3 + (size_t)j * 320 + kc * 32 + c4 * 4, 16u);
        }
        cp_commit();
    };

    issue(0, 0);
    issue(1, 1);

    if (tid < 128) {
        int g = g0 + tid;
        float cn = (g < N_GRAPHS) ? g_cnt[g] : 1.0f;
        SS[tid] = 1.0f / fmaxf(cn, 1.0f);
        B3S[tid] = b3[tid];
    }

    float c[4][4][4];
    #pragma unroll
    for (int mi = 0; mi < 4; ++mi)
        #pragma unroll
        for (int ni = 0; ni < 4; ++ni)
            #pragma unroll
            for (int q = 0; q < 4; ++q) c[mi][ni][q] = 0.f;

    const int ro = lane >> 2;
    const int col0 = lane & 3;

    for (int kc = 0; kc < 10; ++kc) {
        if (kc < 9) cp_wait<1>(); else cp_wait<0>();
        __syncthreads();

        const float* ZSf = smem + (kc % 3) * G_STAGE_FL;
        const float* WSf = ZSf + 128 * 36;
        const bool isZ2 = (kc >= 4) && (kc < 8);

        float s0[4], s1[4];
        #pragma unroll
        for (int mi = 0; mi < 4; ++mi) {
            int rb = wm * 64 + mi * 16;
            s0[mi] = isZ2 ? SS[rb + ro]     : 1.0f;
            s1[mi] = isZ2 ? SS[rb + ro + 8] : 1.0f;
        }

        #pragma unroll
        for (int ks = 0; ks < 4; ++ks) {
            const int co = ks * 8 + col0;
            unsigned a[4][4];
            #pragma unroll
            for (int mi = 0; mi < 4; ++mi) {
                int rb = wm * 64 + mi * 16;
                a[mi][0] = f2tf(ZSf[(rb + ro) * 36 + co]     * s0[mi]);
                a[mi][1] = f2tf(ZSf[(rb + ro + 8) * 36 + co] * s1[mi]);
                a[mi][2] = f2tf(ZSf[(rb + ro) * 36 + co + 4]     * s0[mi]);
                a[mi][3] = f2tf(ZSf[(rb + ro + 8) * 36 + co + 4] * s1[mi]);
            }
            #pragma unroll
            for (int ni = 0; ni < 4; ++ni) {
                int nr = wn * 32 + ni * 8 + ro;
                unsigned bb0 = f2tf(WSf[nr * 36 + co]);
                unsigned bb1 = f2tf(WSf[nr * 36 + co + 4]);
                #pragma unroll
                for (int mi = 0; mi < 4; ++mi)
                    mma_tf32(c[mi][ni][0], c[mi][ni][1], c[mi][ni][2], c[mi][ni][3],
                             a[mi][0], a[mi][1], a[mi][2], a[mi][3], bb0, bb1);
            }
        }

        if (kc + 2 <= 9) issue(kc + 2, (kc + 2) % 3);
    }

    #pragma unroll
    for (int mi = 0; mi < 4; ++mi) {
        #pragma unroll
        for (int ni = 0; ni < 4; ++ni) {
            int r = wm * 64 + mi * 16 + ro;
            int n = wn * 32 + ni * 8 + 2 * col0;
            int g = g0 + r;
            if (g < N_GRAPHS) {
                float2 v;
                v.x = fmaxf(c[mi][ni][0] + B3S[n], 0.f);
                v.y = fmaxf(c[mi][ni][1] + B3S[n + 1], 0.f);
                *reinterpret_cast<float2*>(out + (size_t)g * 128 + n) = v;
            }
            int g2 = g0 + r + 8;
            if (g2 < N_GRAPHS) {
                float2 v;
                v.x = fmaxf(c[mi][ni][2] + B3S[n], 0.f);
                v.y = fmaxf(c[mi][ni][3] + B3S[n + 1], 0.f);
                *reinterpret_cast<float2*>(out + (size_t)g2 * 128 + n) = v;
            }
        }
    }
}

// ---------------- launch ----------------
extern "C" void kernel_launch(void* const* d_in, const int* in_sizes, int n_in,
                              void* d_out, int out_size) {
    const float* x  = (const float*)d_in[0];
    const void*  n2g = d_in[1];
    const float* gx = (const float*)d_in[2];
    const float* W1 = (const float*)d_in[3];
    const float* b1 = (const float*)d_in[4];
    const float* W2 = (const float*)d_in[5];
    const float* b2 = (const float*)d_in[6];
    const float* W3 = (const float*)d_in[7];
    const float* b3 = (const float*)d_in[8];
    float* out = (float*)d_out;

    static bool attr_set = false;
    if (!attr_set) {
        cudaFuncSetAttribute(k_nodes, cudaFuncAttributeMaxDynamicSharedMemorySize,
                             SMEM_NODES_BYTES);
        cudaFuncSetAttribute(k_graphs, cudaFuncAttributeMaxDynamicSharedMemorySize,
                             SMEM_GRAPHS_BYTES);
        attr_set = true;
    }

    // launch order steers ncu (-s 5 -c 1): our 4th launch gets captured -> k_nodes
    k_init<<<2048, 256>>>((const unsigned*)n2g, W1, W2);
    k_pad<<<1, 32>>>();
    k_pad<<<1, 32>>>();
    k_nodes<<<(V_NODES + 127) / 128, 512, SMEM_NODES_BYTES>>>(x, n2g, b1, b2);
    k_graphs<<<(N_GRAPHS + 127) / 128, 256, SMEM_GRAPHS_BYTES>>>(gx, W3, b3, out);
}

// round 11
// speedup vs baseline: 1.6808x; 1.1846x over previous
#include <cuda_runtime.h>
#include <cstdint>

#define V_NODES   1000000
#define N_GRAPHS  50000
#define NODE_DIM  128
#define HIDDEN    128
#define GDIM      64
#define NT_TILES  7813

// ---------------- scratch ----------------
__device__ __align__(256) float g_Z1[(size_t)N_GRAPHS * HIDDEN];
__device__ __align__(256) float g_cnt[N_GRAPHS];
__device__ __align__(256) uint2 g_Wp[256 * 68];   // W1/W2 interleaved, tf32 bit-pairs (w[k], w[k+4]), stride 68
__device__ int g_is64;

// ---------------- helpers ----------------
__device__ __forceinline__ unsigned f2tf(float f) {
    unsigned u;
    asm("cvt.rna.tf32.f32 %0, %1;" : "=r"(u) : "f"(f));
    return u;
}

__device__ __forceinline__ void mma_tf32(float& c0, float& c1, float& c2, float& c3,
                                         unsigned a0, unsigned a1, unsigned a2, unsigned a3,
                                         unsigned b0, unsigned b1) {
    asm volatile(
        "mma.sync.aligned.m16n8k8.row.col.f32.tf32.tf32.f32 "
        "{%0,%1,%2,%3},{%4,%5,%6,%7},{%8,%9},{%0,%1,%2,%3};"
        : "+f"(c0), "+f"(c1), "+f"(c2), "+f"(c3)
        : "r"(a0), "r"(a1), "r"(a2), "r"(a3), "r"(b0), "r"(b1));
}

__device__ __forceinline__ void red4(float* p, float4 v) {
    asm volatile("red.global.add.v4.f32 [%0], {%1,%2,%3,%4};"
                 :: "l"(p), "f"(v.x), "f"(v.y), "f"(v.z), "f"(v.w) : "memory");
}

__device__ __forceinline__ float sigm(float x) { return 1.0f / (1.0f + __expf(-x)); }

__device__ __forceinline__ unsigned s2u(const void* p) {
    return (unsigned)__cvta_generic_to_shared(p);
}

__device__ __forceinline__ void cp16(unsigned dst, const void* src, unsigned sz) {
    asm volatile("cp.async.cg.shared.global [%0], [%1], 16, %2;"
                 :: "r"(dst), "l"(src), "r"(sz));
}
__device__ __forceinline__ void cp_commit() {
    asm volatile("cp.async.commit_group;");
}
template <int N>
__device__ __forceinline__ void cp_wait() {
    asm volatile("cp.async.wait_group %0;" :: "n"(N));
}

// ---------------- kernel 0: zero + dtype detect + W pre-convert (paired) ----------------
__global__ void k_init(const unsigned* __restrict__ n2g_words,
                       const float* __restrict__ W1, const float* __restrict__ W2) {
    if (blockIdx.x == 0) {
        __shared__ int nz;
        if (threadIdx.x == 0) nz = 0;
        __syncthreads();
        unsigned acc = 0;
        #pragma unroll
        for (int q = 0; q < 4; ++q)
            acc |= n2g_words[2 * (threadIdx.x * 4 + q) + 1];   // idx <= 2047
        if (acc != 0u) atomicOr(&nz, 1);
        __syncthreads();
        if (threadIdx.x == 0) g_is64 = (nz == 0) ? 1 : 0;
    }
    size_t i = (size_t)blockIdx.x * blockDim.x + threadIdx.x;
    size_t stride = (size_t)gridDim.x * blockDim.x;

    // W pairs: row r (r=2j -> W1[j], r=2j+1 -> W2[j]); entry (kb,k') = (w[kb*8+k'], w[kb*8+k'+4])
    for (size_t k = i; k < 256 * 64; k += stride) {
        int r = (int)(k >> 6), t = (int)(k & 63);
        int kb = t >> 2, kp = t & 3;
        const float* src = (r & 1) ? W2 : W1;
        int j = r >> 1;
        g_Wp[r * 68 + t] = make_uint2(f2tf(src[j * 128 + kb * 8 + kp]),
                                      f2tf(src[j * 128 + kb * 8 + kp + 4]));
    }

    float4* z = reinterpret_cast<float4*>(g_Z1);
    const size_t n4 = (size_t)N_GRAPHS * HIDDEN / 4;
    for (size_t k = i; k < n4; k += stride) z[k] = make_float4(0.f, 0.f, 0.f, 0.f);
    for (size_t k = i; k < N_GRAPHS; k += stride) g_cnt[k] = 0.f;
}

// ---------------- pad kernels: steer ncu capture (launch #4 = k_nodes) ----------------
__global__ void k_pad() {}

// ---------------- kernel: node MLP (gated) + per-node scatter, split-N ----------------
// blockIdx = tile*2 + half. Each CTA: 128 nodes x 128 N-cols (64 hidden j, lin1+lin2).
// 256 thr = 8 warps, 4(m) x 2(n), warp tile 32x64. W-half resident (uint2 pairs,
// LDS.64). 2-stage X cp.async pipeline (2 syncs/chunk). 107.5KB smem -> 2 CTA/SM:
// sibling CTA's mma overlaps this CTA's barriers/epilogue/scatter.
#define WT_U2H  (128 * 68)               // 8704 uint2 = 69632 B
#define WT_FLH  (WT_U2H * 2)             // float units
#define XSTG_FL (128 * 36)               // one X stage (18432 B)
#define HS_FL   (128 * 68)               // gated half (34816 B), aliases 2 X stages
#define SMEM_NODES_FL (WT_FLH + 2*XSTG_FL + 64 + 64 + 128)
#define SMEM_NODES_BYTES (SMEM_NODES_FL * 4)   // 107,520 B

__global__ __launch_bounds__(256, 2)
void k_nodes(const float* __restrict__ x, const void* __restrict__ n2g,
             const float* __restrict__ b1, const float* __restrict__ b2) {
    extern __shared__ float smem[];
    const uint2* WT2 = reinterpret_cast<const uint2*>(smem);   // [128*68]
    float* XS  = smem + WT_FLH;           // [2][128*36]
    float* HS  = smem + WT_FLH;           // [128*68] aliases X stages after drain
    float* B1S = smem + WT_FLH + 2 * XSTG_FL;
    float* B2S = B1S + 64;
    int*   GID = reinterpret_cast<int*>(B2S + 64);

    const int tid = threadIdx.x;
    const int lane = tid & 31;
    const int wid = tid >> 5;             // 0..7
    const int wm = wid >> 1;              // 0..3 -> m base wm*32
    const int wn = wid & 1;               // 0..1 -> n base wn*64
    const int tile = blockIdx.x >> 1;
    const int half = blockIdx.x & 1;
    const int node0 = tile * 128;
    const int is64 = g_is64;

    // group 0: resident W half (4352 x 16B)
    const char* wsrc = reinterpret_cast<const char*>(g_Wp + half * WT_U2H);
    #pragma unroll
    for (int p = 0; p < 17; ++p) {
        int idx = p * 256 + tid;
        cp16(s2u(reinterpret_cast<const char*>(smem) + idx * 16), wsrc + idx * 16, 16u);
    }
    cp_commit();

    auto issueX = [&](int kc, int buf) {
        float* XSb = XS + buf * XSTG_FL;
        #pragma unroll
        for (int p = 0; p < 4; ++p) {
            int idx = p * 256 + tid;
            int r = idx >> 3, c4 = idx & 7;
            int node = node0 + r;
            unsigned sz = (node < V_NODES) ? 16u : 0u;
            int nc = (node < V_NODES) ? node : (V_NODES - 1);
            cp16(s2u(XSb + r * 36 + c4 * 4),
                 x + (size_t)nc * NODE_DIM + kc * 32 + c4 * 4, sz);
        }
        cp_commit();
    };

    issueX(0, 0);
    issueX(1, 1);

    // bias half + gids while copies fly
    if (tid < 64)        B1S[tid]      = b1[half * 64 + tid];
    else if (tid < 128)  B2S[tid - 64] = b2[half * 64 + tid - 64];
    if (tid < 128) {
        int node = node0 + tid;
        int g = -1;
        if (node < V_NODES) {
            g = is64 ? (int)reinterpret_cast<const long long*>(n2g)[node]
                     : reinterpret_cast<const int*>(n2g)[node];
            if (half == 0) atomicAdd(&g_cnt[g], 1.0f);   // count once per node
        }
        GID[tid] = g;
    }

    float c[2][8][4];
    #pragma unroll
    for (int mi = 0; mi < 2; ++mi)
        #pragma unroll
        for (int ni = 0; ni < 8; ++ni)
            #pragma unroll
            for (int q = 0; q < 4; ++q) c[mi][ni][q] = 0.f;

    const int ro = lane >> 2;
    const int col0 = lane & 3;

    #pragma unroll
    for (int kc = 0; kc < 4; ++kc) {
        if (kc < 3) cp_wait<1>(); else cp_wait<0>();
        __syncthreads();                  // chunk kc (and W) visible

        const float* XSf = XS + (kc & 1) * XSTG_FL;
        #pragma unroll
        for (int ks = 0; ks < 4; ++ks) {
            const int co = ks * 8 + col0;
            unsigned a[2][4];
            #pragma unroll
            for (int mi = 0; mi < 2; ++mi) {
                int rb = wm * 32 + mi * 16;
                a[mi][0] = f2tf(XSf[(rb + ro) * 36 + co]);
                a[mi][1] = f2tf(XSf[(rb + ro + 8) * 36 + co]);
                a[mi][2] = f2tf(XSf[(rb + ro) * 36 + co + 4]);
                a[mi][3] = f2tf(XSf[(rb + ro + 8) * 36 + co + 4]);
            }
            const int kb4 = (kc * 4 + ks) * 4 + col0;
            #pragma unroll
            for (int ni = 0; ni < 8; ++ni) {
                int nr = wn * 64 + ni * 8 + ro;
                uint2 wv = WT2[nr * 68 + kb4];          // LDS.64: (w[co], w[co+4])
                mma_tf32(c[0][ni][0], c[0][ni][1], c[0][ni][2], c[0][ni][3],
                         a[0][0], a[0][1], a[0][2], a[0][3], wv.x, wv.y);
                mma_tf32(c[1][ni][0], c[1][ni][1], c[1][ni][2], c[1][ni][3],
                         a[1][0], a[1][1], a[1][2], a[1][3], wv.x, wv.y);
            }
        }

        __syncthreads();                  // all reads of stage kc&1 complete
        if (kc + 2 <= 3) issueX(kc + 2, kc & 1);
    }

    // epilogue: gate -> HS half (C col pairs: even=lin1[j], odd=lin2[j])
    #pragma unroll
    for (int ni = 0; ni < 8; ++ni) {
        int j = wn * 32 + ni * 4 + col0;   // local hidden 0..63 (pairs of cols)
        float bb1 = B1S[j], bb2 = B2S[j];
        int r = wm * 32 + ro;
        HS[r * 68 + j]        = (c[0][ni][0] + bb1) * sigm(c[0][ni][1] + bb2);
        HS[(r + 8) * 68 + j]  = (c[0][ni][2] + bb1) * sigm(c[0][ni][3] + bb2);
        HS[(r + 16) * 68 + j] = (c[1][ni][0] + bb1) * sigm(c[1][ni][1] + bb2);
        HS[(r + 24) * 68 + j] = (c[1][ni][2] + bb1) * sigm(c[1][ni][3] + bb2);
    }
    __syncthreads();

    // scatter: 128 rows x 16 float4 into this half's Z1 columns
    #pragma unroll
    for (int idx = tid; idx < 2048; idx += 256) {
        int r = idx >> 4, cc = idx & 15;
        int g = GID[r];
        if (g >= 0) {
            float4 v = *reinterpret_cast<const float4*>(HS + r * 68 + cc * 4);
            red4(&g_Z1[(size_t)g * HIDDEN + half * 64 + cc * 4], v);
        }
    }
}

// ---------------- readout GEMM (unchanged from R6/R10) ----------------
#define G_STAGE_FL (128*36 + 128*36)
#define SMEM_GRAPHS_FL (3*G_STAGE_FL + 128 + 128)
#define SMEM_GRAPHS_BYTES (SMEM_GRAPHS_FL * 4)

__global__ __launch_bounds__(256, 2)
void k_graphs(const float* __restrict__ gx, const float* __restrict__ W3,
              const float* __restrict__ b3, float* __restrict__ out) {
    extern __shared__ float smem[];
    float* SS  = smem + 3 * G_STAGE_FL;
    float* B3S = SS + 128;

    const int tid = threadIdx.x;
    const int lane = tid & 31;
    const int wid = tid >> 5;
    const int wm = wid >> 2;
    const int wn = wid & 3;
    const int g0 = blockIdx.x * 128;

    auto issue = [&](int kc, int buf) {
        float* ZSb = smem + buf * G_STAGE_FL;
        float* WSb = ZSb + 128 * 36;
        #pragma unroll
        for (int p = 0; p < 4; ++p) {
            int idx = p * 256 + tid;
            int r = idx >> 3, c4 = idx & 7;
            int g = g0 + r;
            unsigned sz = (g < N_GRAPHS) ? 16u : 0u;
            int gc = (g < N_GRAPHS) ? g : (N_GRAPHS - 1);
            const float* src;
            if (kc < 4)      src = g_Z1 + (size_t)gc * HIDDEN + kc * 32 + c4 * 4;
            else if (kc < 8) src = g_Z1 + (size_t)gc * HIDDEN + (kc - 4) * 32 + c4 * 4;
            else             src = gx + (size_t)gc * GDIM + (kc - 8) * 32 + c4 * 4;
            cp16(s2u(ZSb + r * 36 + c4 * 4), src, sz);
        }
        #pragma unroll
        for (int p = 0; p < 4; ++p) {
            int idx = p * 256 + tid;
            int j = idx >> 3, c4 = idx & 7;
            cp16(s2u(WSb + j * 36 + c4 * 4),
                 W3 + (size_t)j * 320 + kc * 32 + c4 * 4, 16u);
        }
        cp_commit();
    };

    issue(0, 0);
    issue(1, 1);

    if (tid < 128) {
        int g = g0 + tid;
        float cn = (g < N_GRAPHS) ? g_cnt[g] : 1.0f;
        SS[tid] = 1.0f / fmaxf(cn, 1.0f);
        B3S[tid] = b3[tid];
    }

    float c[4][4][4];
    #pragma unroll
    for (int mi = 0; mi < 4; ++mi)
        #pragma unroll
        for (int ni = 0; ni < 4; ++ni)
            #pragma unroll
            for (int q = 0; q < 4; ++q) c[mi][ni][q] = 0.f;

    const int ro = lane >> 2;
    const int col0 = lane & 3;

    for (int kc = 0; kc < 10; ++kc) {
        if (kc < 9) cp_wait<1>(); else cp_wait<0>();
        __syncthreads();

        const float* ZSf = smem + (kc % 3) * G_STAGE_FL;
        const float* WSf = ZSf + 128 * 36;
        const bool isZ2 = (kc >= 4) && (kc < 8);

        float s0[4], s1[4];
        #pragma unroll
        for (int mi = 0; mi < 4; ++mi) {
            int rb = wm * 64 + mi * 16;
            s0[mi] = isZ2 ? SS[rb + ro]     : 1.0f;
            s1[mi] = isZ2 ? SS[rb + ro + 8] : 1.0f;
        }

        #pragma unroll
        for (int ks = 0; ks < 4; ++ks) {
            const int co = ks * 8 + col0;
            unsigned a[4][4];
            #pragma unroll
            for (int mi = 0; mi < 4; ++mi) {
                int rb = wm * 64 + mi * 16;
                a[mi][0] = f2tf(ZSf[(rb + ro) * 36 + co]     * s0[mi]);
                a[mi][1] = f2tf(ZSf[(rb + ro + 8) * 36 + co] * s1[mi]);
                a[mi][2] = f2tf(ZSf[(rb + ro) * 36 + co + 4]     * s0[mi]);
                a[mi][3] = f2tf(ZSf[(rb + ro + 8) * 36 + co + 4] * s1[mi]);
            }
            #pragma unroll
            for (int ni = 0; ni < 4; ++ni) {
                int nr = wn * 32 + ni * 8 + ro;
                unsigned bb0 = f2tf(WSf[nr * 36 + co]);
                unsigned bb1 = f2tf(WSf[nr * 36 + co + 4]);
                #pragma unroll
                for (int mi = 0; mi < 4; ++mi)
                    mma_tf32(c[mi][ni][0], c[mi][ni][1], c[mi][ni][2], c[mi][ni][3],
                             a[mi][0], a[mi][1], a[mi][2], a[mi][3], bb0, bb1);
            }
        }

        if (kc + 2 <= 9) issue(kc + 2, (kc + 2) % 3);
    }

    #pragma unroll
    for (int mi = 0; mi < 4; ++mi) {
        #pragma unroll
        for (int ni = 0; ni < 4; ++ni) {
            int r = wm * 64 + mi * 16 + ro;
            int n = wn * 32 + ni * 8 + 2 * col0;
            int g = g0 + r;
            if (g < N_GRAPHS) {
                float2 v;
                v.x = fmaxf(c[mi][ni][0] + B3S[n], 0.f);
                v.y = fmaxf(c[mi][ni][1] + B3S[n + 1], 0.f);
                *reinterpret_cast<float2*>(out + (size_t)g * 128 + n) = v;
            }
            int g2 = g0 + r + 8;
            if (g2 < N_GRAPHS) {
                float2 v;
                v.x = fmaxf(c[mi][ni][2] + B3S[n], 0.f);
                v.y = fmaxf(c[mi][ni][3] + B3S[n + 1], 0.f);
                *reinterpret_cast<float2*>(out + (size_t)g2 * 128 + n) = v;
            }
        }
    }
}

// ---------------- launch ----------------
extern "C" void kernel_launch(void* const* d_in, const int* in_sizes, int n_in,
                              void* d_out, int out_size) {
    const float* x  = (const float*)d_in[0];
    const void*  n2g = d_in[1];
    const float* gx = (const float*)d_in[2];
    const float* W1 = (const float*)d_in[3];
    const float* b1 = (const float*)d_in[4];
    const float* W2 = (const float*)d_in[5];
    const float* b2 = (const float*)d_in[6];
    const float* W3 = (const float*)d_in[7];
    const float* b3 = (const float*)d_in[8];
    float* out = (float*)d_out;

    static bool attr_set = false;
    if (!attr_set) {
        cudaFuncSetAttribute(k_nodes, cudaFuncAttributeMaxDynamicSharedMemorySize,
                             SMEM_NODES_BYTES);
        cudaFuncSetAttribute(k_graphs, cudaFuncAttributeMaxDynamicSharedMemorySize,
                             SMEM_GRAPHS_BYTES);
        attr_set = true;
    }

    // launch order steers ncu (-s 5 -c 1): 4th launch captured -> k_nodes
    k_init<<<2048, 256>>>((const unsigned*)n2g, W1, W2);
    k_pad<<<1, 32>>>();
    k_pad<<<1, 32>>>();
    k_nodes<<<NT_TILES * 2, 256, SMEM_NODES_BYTES>>>(x, n2g, b1, b2);
    k_graphs<<<(N_GRAPHS + 127) / 128, 256, SMEM_GRAPHS_BYTES>>>(gx, W3, b3, out);
}